// round 14
// baseline (speedup 1.0000x reference)
#include <cuda_runtime.h>
#include <cuda_bf16.h>
#include <math.h>
#include <stdint.h>

#define B_ 128
#define T_ 512
#define F_ 256
#define H_ 512
#define NG 2048               // H_*4 fused gate cols, n = h*4+g
#define NBLK 128
#define NTHR 256

// ---------------- device globals (allocation-free scratch) ------------------
__device__ float g_xproj[(size_t)T_ * B_ * NG];             // [t][b][n]
__device__ unsigned char g_xs[2][(size_t)B_ * T_ * F_ * 2]; // bf16 hi/lo, pre-swizzled
__device__ unsigned char g_wt[2][(size_t)NG * F_ * 2];      // bf16 hi/lo W^T, pre-swizzled
__device__ float g_bc[NG];                                  // fused bias
__device__ __nv_bfloat16 g_hbf[2][2][B_][H_];               // [parity][hi/lo][b][k]
__device__ volatile unsigned g_arrive4[4 * 32];             // 128B-spaced per-group
__device__ volatile unsigned g_release4[4 * 32];

// ---------------------------------------------------------------------------
__device__ __forceinline__ uint32_t smem_u32(const void* p) {
    uint32_t a;
    asm("{ .reg .u64 t; cvta.to.shared.u64 t, %1; cvt.u32.u64 %0, t; }" : "=r"(a) : "l"(p));
    return a;
}
__device__ __forceinline__ void cpasync16(uint32_t dst_smem, const void* src) {
    asm volatile("cp.async.cg.shared.global [%0], [%1], 16;\n"
                 :: "r"(dst_smem), "l"(src));
}
__device__ __forceinline__ void ldsm4(uint32_t* r, uint32_t addr) {
    asm volatile("ldmatrix.sync.aligned.m8n8.x4.shared.b16 {%0,%1,%2,%3}, [%4];"
                 : "=r"(r[0]), "=r"(r[1]), "=r"(r[2]), "=r"(r[3]) : "r"(addr));
}
__device__ __forceinline__ void mma16816(float* d, const uint32_t* a,
                                         uint32_t b0, uint32_t b1) {
    asm volatile(
        "mma.sync.aligned.m16n8k16.row.col.f32.bf16.bf16.f32 "
        "{%0,%1,%2,%3}, {%4,%5,%6,%7}, {%8,%9}, {%0,%1,%2,%3};"
        : "+f"(d[0]), "+f"(d[1]), "+f"(d[2]), "+f"(d[3])
        : "r"(a[0]), "r"(a[1]), "r"(a[2]), "r"(a[3]), "r"(b0), "r"(b1));
}

// ---------------------------------------------------------------------------
__global__ void init_kernel() {
    int i = blockIdx.x * blockDim.x + threadIdx.x;
    if (i < 2 * B_ * H_) ((__nv_bfloat16*)g_hbf[0])[i] = __float2bfloat16(0.f);
    if (i < 4 * 32) { g_arrive4[i] = 0u; g_release4[i] = 0u; }
}

// ---------------------------------------------------------------------------
__global__ __launch_bounds__(256) void split_x_kernel(const float* __restrict__ x) {
    int idx = blockIdx.x * 256 + threadIdx.x;
    int m = idx >> 5;
    int u = idx & 31;
    float v[8];
    *(float4*)&v[0] = *(const float4*)&x[(size_t)m * F_ + u * 8];
    *(float4*)&v[4] = *(const float4*)&x[(size_t)m * F_ + u * 8 + 4];
    __nv_bfloat16 hi[8], lo[8];
#pragma unroll
    for (int i = 0; i < 8; i++) {
        hi[i] = __float2bfloat16(v[i]);
        lo[i] = __float2bfloat16(v[i] - __bfloat162float(hi[i]));
    }
    int key = (m >> 9) & 7;
    size_t dst = (size_t)m * 512 + ((u ^ key) << 4);
    *(uint4*)(g_xs[0] + dst) = *(uint4*)hi;
    *(uint4*)(g_xs[1] + dst) = *(uint4*)lo;
}

// ---------------------------------------------------------------------------
__global__ __launch_bounds__(256) void split_w_kernel(
    const float* __restrict__ W0, const float* __restrict__ b0v,
    const float* __restrict__ W1, const float* __restrict__ b1v,
    const float* __restrict__ W2, const float* __restrict__ b2v,
    const float* __restrict__ W3, const float* __restrict__ b3v)
{
    int idx = blockIdx.x * 256 + threadIdx.x;
    int n = idx >> 5;
    int u = idx & 31;
    int h = n >> 2, g = n & 3;
    const float* W = (g == 0) ? W0 : (g == 1) ? W1 : (g == 2) ? W2 : W3;
    __nv_bfloat16 hi[8], lo[8];
#pragma unroll
    for (int i = 0; i < 8; i++) {
        float v = W[(size_t)(u * 8 + i) * H_ + h];
        hi[i] = __float2bfloat16(v);
        lo[i] = __float2bfloat16(v - __bfloat162float(hi[i]));
    }
    size_t dst = (size_t)n * 512 + ((u ^ (n & 7)) << 4);
    *(uint4*)(g_wt[0] + dst) = *(uint4*)hi;
    *(uint4*)(g_wt[1] + dst) = *(uint4*)lo;
    if (u == 0) {
        const float* bias = (g == 0) ? b0v : (g == 1) ? b1v : (g == 2) ? b2v : b3v;
        g_bc[n] = bias[h];
    }
}

// ---------------------------------------------------------------------------
// Proj GEMM (tensor) — unchanged.
// ---------------------------------------------------------------------------
#define PJ_A   0
#define PJ_B   65536
#define PJ_TOT 98304

__global__ __launch_bounds__(256) void proj_mma_kernel() {
    extern __shared__ __align__(1024) char smem[];
    const uint32_t sb = smem_u32(smem);

    const int t    = blockIdx.y;
    const int n0   = blockIdx.x * 64;
    const int tid  = threadIdx.x;
    const int w    = tid >> 5;
    const int lane = tid & 31;
    const int lrow = lane & 15;
    const int lku  = lane >> 4;

    float2 bias_r[4][2];
#pragma unroll
    for (int nt = 0; nt < 4; nt++)
#pragma unroll
        for (int hf = 0; hf < 2; hf++) {
            int col = n0 + nt * 16 + hf * 8 + (lane & 3) * 2;
            bias_r[nt][hf] = *(const float2*)&g_bc[col];
        }

    auto load_chunk = [&](int c, int buf) {
#pragma unroll
        for (int i = 0; i < 8; i++) {
            int lin = i * 256 + tid;
            int hl = lin >> 10;
            int r  = lin & 1023;
            int b  = r >> 3;
            int uu = r & 7;
            const void* src = g_xs[hl] + ((size_t)(b * T_ + t) * 512 + c * 128 + uu * 16);
            cpasync16(sb + PJ_A + buf * 32768 + hl * 16384 + b * 128 + uu * 16, src);
        }
#pragma unroll
        for (int i = 0; i < 4; i++) {
            int lin = i * 256 + tid;
            int hl = lin >> 9;
            int r  = lin & 511;
            int nl = r >> 3;
            int uu = r & 7;
            const void* src = g_wt[hl] + ((size_t)(n0 + nl) * 512 + c * 128 + uu * 16);
            cpasync16(sb + PJ_B + buf * 16384 + hl * 8192 + nl * 128 + uu * 16, src);
        }
        asm volatile("cp.async.commit_group;\n");
    };

    load_chunk(0, 0);

    float acc[4][2][4] = {};

    for (int c = 0; c < 4; c++) {
        const int buf = c & 1;
        asm volatile("cp.async.wait_group 0;\n" ::: "memory");
        __syncthreads();
        if (c + 1 < 4) load_chunk(c + 1, buf ^ 1);

        const uint32_t a_base = sb + PJ_A + buf * 32768 + (w * 16 + lrow) * 128;
        const uint32_t b_base = sb + PJ_B + buf * 16384;
        const uint32_t asw = (uint32_t)(lrow & 7);

#pragma unroll
        for (int j = 0; j < 4; j++) {
            uint32_t au = (uint32_t)(j * 2 + lku);
            uint32_t ah[4], al[4];
            ldsm4(ah, a_base + ((au ^ asw) << 4));
            ldsm4(al, a_base + 16384 + ((au ^ asw) << 4));

#pragma unroll
            for (int nt = 0; nt < 4; nt++) {
                uint32_t brow = b_base + (nt * 16 + lrow) * 128;
                uint32_t bh[4], bl[4];
                ldsm4(bh, brow + ((au ^ asw) << 4));
                ldsm4(bl, brow + 8192 + ((au ^ asw) << 4));

                mma16816(acc[nt][0], ah, bh[0], bh[2]);
                mma16816(acc[nt][0], ah, bl[0], bl[2]);
                mma16816(acc[nt][0], al, bh[0], bh[2]);
                mma16816(acc[nt][1], ah, bh[1], bh[3]);
                mma16816(acc[nt][1], ah, bl[1], bl[3]);
                mma16816(acc[nt][1], al, bh[1], bh[3]);
            }
        }
        __syncthreads();
    }

    const int r0 = w * 16 + (lane >> 2);
#pragma unroll
    for (int nt = 0; nt < 4; nt++)
#pragma unroll
        for (int hf = 0; hf < 2; hf++) {
            int col = n0 + nt * 16 + hf * 8 + (lane & 3) * 2;
            float2 bb = bias_r[nt][hf];
            *(float2*)&g_xproj[((size_t)t * B_ + r0) * NG + col] =
                make_float2(acc[nt][hf][0] + bb.x, acc[nt][hf][1] + bb.y);
            *(float2*)&g_xproj[((size_t)t * B_ + r0 + 8) * NG + col] =
                make_float2(acc[nt][hf][2] + bb.x, acc[nt][hf][3] + bb.y);
        }
}

// ---------------------------------------------------------------------------
// Persistent recurrent kernel (R13 + warp-specialized half loads):
//   bg = bid>>5, cg = bid&31; per-bg group barrier; split-K warps
//   (wn = w&3: 16 n-cols; wk = w>>2: k-half). NEW: each k-half group
//   (threads wk*128..wk*128+127) loads ONLY its own 32KB half and syncs on a
//   named barrier (bar.sync 1+wk, 128) — halves load in parallel and each
//   group starts mma as soon as its half lands.
// ---------------------------------------------------------------------------
#define SMB_A    0            // [2 hl][8 kt][32 m][128B] = 65536
#define SMB_B    65536        // [2 hl][64 n][1024 B]     = 131072
#define SMB_XS   196608       // [32 b][272 B] = 8704
#define SMB_PRE  205312       // 2 x float[64 n][36 m] = 18432
#define SMB_TOT  223744

__global__ __launch_bounds__(NTHR) void recurrent_kernel(
    const float* __restrict__ Rf, const float* __restrict__ Ri,
    const float* __restrict__ Ro, const float* __restrict__ Rz)
{
    extern __shared__ __align__(1024) char smem[];
    const uint32_t sb = smem_u32(smem);

    const int bid  = blockIdx.x;
    const int tid  = threadIdx.x;
    const int w    = tid >> 5;
    const int lane = tid & 31;
    const int bg   = bid >> 5;       // batch group 0..3
    const int cg   = bid & 31;       // col group 0..31

    float* xsf = (float*)(smem + SMB_XS);
    float* pre = (float*)(smem + SMB_PRE);   // two banks of 2304 floats

    // stage split R^T slice (once): row n = h_loc*4+g (64 rows), 512 k
    {
        const float* Rm[4] = {Rf, Ri, Ro, Rz};
        for (int idx = tid; idx < 64 * H_; idx += NTHR) {
            int n = idx & 63;
            int k = idx >> 6;
            int hl = n >> 2, g = n & 3;
            float v = Rm[g][(size_t)k * H_ + cg * 16 + hl];
            __nv_bfloat16 vhi = __float2bfloat16(v);
            __nv_bfloat16 vlo = __float2bfloat16(v - __bfloat162float(vhi));
            uint32_t off = n * 1024 + ((((uint32_t)k >> 3) ^ (n & 7)) << 4) + (k & 7) * 2;
            *(__nv_bfloat16*)(smem + SMB_B + off) = vhi;
            *(__nv_bfloat16*)(smem + SMB_B + 65536 + off) = vlo;
        }
    }

    // prefetch xproj[0] slice
    {
#pragma unroll
        for (int e = 0; e < 2; e++) {
            int idx = e * NTHR + tid;
            int b = idx >> 4, u = idx & 15;
            const void* src = g_xproj + (size_t)(bg * 32 + b) * NG + cg * 64 + u * 4;
            cpasync16(sb + SMB_XS + b * 272 + u * 16, src);
        }
        asm volatile("cp.async.commit_group;\n");
    }
    __syncthreads();

    // split-K MMA mapping: wn = n-tile (16 cols), wk = k-half (256 k)
    const int wn = w & 3;
    const int wk = w >> 2;
    const int lrow = lane & 15;
    const int lku  = lane >> 4;
    const uint32_t lsw    = (uint32_t)(lrow & 7);
    const uint32_t a_base = sb + SMB_A + lrow * 128;
    const uint32_t b_base = sb + SMB_B + (wn * 16 + lrow) * 1024;
    float* preh = pre + wk * 2304;

    // half-load mapping: group wk loads kt wk*4..wk*4+3, 16 x16B per thread
    const int lu = tid & 127;

    // update mapping
    const int ub = tid >> 3;
    const int uq = tid & 7;
    float c_reg[2] = {0.f, 0.f};
    float n_reg[2] = {0.f, 0.f};

    volatile unsigned* arr = &g_arrive4[bg * 32];
    volatile unsigned* rel = &g_release4[bg * 32];
    unsigned epoch = 0;

    for (int t = 0; t < T_; t++) {
        const int par = t & 1;
        const __nv_bfloat16* __restrict__ hsrc = &g_hbf[par][0][0][0];

        // ---- warp-specialized A half-load: group wk loads its own 32KB ----
        {
#pragma unroll
            for (int i = 0; i < 16; i++) {
                int lin = i * 128 + lu;        // 0..2047 within the half
                int hl = lin >> 10;
                int r  = lin & 1023;
                int kt = wk * 4 + (r >> 8);
                int m  = (r >> 3) & 31;
                int s  = r & 7;
                const __nv_bfloat16* src =
                    hsrc + ((size_t)hl * B_ + bg * 32 + m) * H_ + kt * 64 + s * 8;
                cpasync16(sb + SMB_A + hl * 32768 + kt * 4096 +
                          m * 128 + ((s ^ (m & 7)) << 4), src);
            }
            asm volatile("cp.async.commit_group;\n");
            asm volatile("cp.async.wait_group 0;\n" ::: "memory");
            // group-local barrier: my half fully visible to my 4 warps
            asm volatile("bar.sync %0, 128;" :: "r"(1 + wk) : "memory");
        }

        float acc[2][2][4] = {};   // [mt][n8][4]

#pragma unroll
        for (int j = 0; j < 16; j++) {
            const int kt = wk * 4 + (j >> 2);
            const uint32_t au = (uint32_t)((j & 3) * 2 + lku);
            const uint32_t bu = (uint32_t)(wk * 32 + j * 2 + lku);

            const uint32_t a_hi0 = a_base + kt * 4096 + ((au ^ lsw) << 4);
            const uint32_t a_hi1 = a_hi0 + 2048;
            const uint32_t b_hi  = b_base + ((bu ^ lsw) << 4);

            uint32_t ah0[4], ah1[4], al0[4], al1[4], bh[4], bl[4];
            ldsm4(ah0, a_hi0);
            ldsm4(ah1, a_hi1);
            ldsm4(al0, a_hi0 + 32768);
            ldsm4(al1, a_hi1 + 32768);
            ldsm4(bh, b_hi);
            ldsm4(bl, b_hi + 65536);

            mma16816(acc[0][0], ah0, bh[0], bh[2]);
            mma16816(acc[0][0], ah0, bl[0], bl[2]);
            mma16816(acc[0][0], al0, bh[0], bh[2]);
            mma16816(acc[0][1], ah0, bh[1], bh[3]);
            mma16816(acc[0][1], ah0, bl[1], bl[3]);
            mma16816(acc[0][1], al0, bh[1], bh[3]);

            mma16816(acc[1][0], ah1, bh[0], bh[2]);
            mma16816(acc[1][0], ah1, bl[0], bl[2]);
            mma16816(acc[1][0], al1, bh[0], bh[2]);
            mma16816(acc[1][1], ah1, bh[1], bh[3]);
            mma16816(acc[1][1], ah1, bl[1], bl[3]);
            mma16816(acc[1][1], al1, bh[1], bh[3]);
        }

        // epilogue: D fragments -> preh[n][m] (bank wk, stride 36)
        {
            int r0 = lane >> 2;
#pragma unroll
            for (int mt = 0; mt < 2; mt++) {
                int row0 = mt * 16 + r0;
#pragma unroll
                for (int n8 = 0; n8 < 2; n8++) {
                    int col0 = wn * 16 + n8 * 8 + (lane & 3) * 2;
                    preh[(col0    ) * 36 + row0    ] = acc[mt][n8][0];
                    preh[(col0 + 1) * 36 + row0    ] = acc[mt][n8][1];
                    preh[(col0    ) * 36 + row0 + 8] = acc[mt][n8][2];
                    preh[(col0 + 1) * 36 + row0 + 8] = acc[mt][n8][3];
                }
            }
        }
        __syncthreads();

        // pointwise sLSTM update (sum the two k-half banks)
        {
            const int np = par ^ 1;
            const int gb = bg * 32 + ub;
            uint32_t phi, plo;
            __nv_bfloat16* vhi = (__nv_bfloat16*)&phi;
            __nv_bfloat16* vlo = (__nv_bfloat16*)&plo;
#pragma unroll
            for (int e = 0; e < 2; e++) {
                int hc = uq * 2 + e;
                float ft = pre[(hc * 4 + 0) * 36 + ub] + pre[2304 + (hc * 4 + 0) * 36 + ub]
                         + xsf[ub * 68 + hc * 4 + 0];
                float it = pre[(hc * 4 + 1) * 36 + ub] + pre[2304 + (hc * 4 + 1) * 36 + ub]
                         + xsf[ub * 68 + hc * 4 + 1];
                float ot = pre[(hc * 4 + 2) * 36 + ub] + pre[2304 + (hc * 4 + 2) * 36 + ub]
                         + xsf[ub * 68 + hc * 4 + 2];
                float zt = pre[(hc * 4 + 3) * 36 + ub] + pre[2304 + (hc * 4 + 3) * 36 + ub]
                         + xsf[ub * 68 + hc * 4 + 3];

                float o  = __fdividef(1.f, 1.f + __expf(-ot));
                float z  = 1.f - __fdividef(2.f, __expf(2.f * zt) + 1.f);
                float fh = __expf(fminf(ft, 10.f));
                float ih = __expf(fminf(it, 10.f));
                float rd = __fdividef(1.f, fh + ih + 1e-8f);
                float f  = fh * rd;
                float ii = ih * rd;
                c_reg[e] = f * c_reg[e] + ii * z;
                n_reg[e] = f * n_reg[e] + ii;
                float hv = o * __fdividef(c_reg[e], n_reg[e] + 1e-8f);

                vhi[e] = __float2bfloat16(hv);
                vlo[e] = __float2bfloat16(hv - __bfloat162float(vhi[e]));
            }
            *(uint32_t*)&g_hbf[np][0][gb][cg * 16 + uq * 2] = phi;
            *(uint32_t*)&g_hbf[np][1][gb][cg * 16 + uq * 2] = plo;
        }

        __syncthreads();

        // prefetch xproj[t+1] in barrier shadow
        if (t + 1 < T_) {
#pragma unroll
            for (int e = 0; e < 2; e++) {
                int idx = e * NTHR + tid;
                int b = idx >> 4, u = idx & 15;
                const void* src = g_xproj + ((size_t)(t + 1) * B_ + bg * 32 + b) * NG
                                + cg * 64 + u * 4;
                cpasync16(sb + SMB_XS + b * 272 + u * 16, src);
            }
            asm volatile("cp.async.commit_group;\n");
        }

        // ---- per-bg group barrier (32 blocks) ----
        epoch++;
        if (tid == 0) {
            __threadfence();
            unsigned a = atomicAdd((unsigned*)arr, 1u) + 1u;
            if (a == epoch * 32) {
                *rel = epoch;
                __threadfence();
            } else {
                while (*rel < epoch) { }
                __threadfence();
            }
        }
        __syncthreads();
    }

    asm volatile("cp.async.wait_group 0;\n" ::: "memory");
}

// ---------------------------------------------------------------------------
__global__ __launch_bounds__(128) void head_kernel(
    const float* __restrict__ fcw, const float* __restrict__ fcb,
    float* __restrict__ out)
{
    int b = blockIdx.x;
    float s = 0.f;
    for (int k = threadIdx.x; k < H_; k += 128) {
        float hv = __bfloat162float(g_hbf[0][0][b][k]) +
                   __bfloat162float(g_hbf[0][1][b][k]);
        s += hv * fcw[k];
    }

    __shared__ float red[4];
#pragma unroll
    for (int off = 16; off; off >>= 1)
        s += __shfl_down_sync(0xffffffff, s, off);
    if ((threadIdx.x & 31) == 0) red[threadIdx.x >> 5] = s;
    __syncthreads();
    if (threadIdx.x == 0) {
        float tot = red[0] + red[1] + red[2] + red[3];
        out[b] = tanhf(tot + fcb[0]);
    }
}

// ---------------------------------------------------------------------------
extern "C" void kernel_launch(void* const* d_in, const int* in_sizes, int n_in,
                              void* d_out, int out_size)
{
    const float* x   = (const float*)d_in[0];
    const float* Wf  = (const float*)d_in[1];
    const float* bf  = (const float*)d_in[2];
    const float* Wi  = (const float*)d_in[3];
    const float* bi  = (const float*)d_in[4];
    const float* Wo  = (const float*)d_in[5];
    const float* bo  = (const float*)d_in[6];
    const float* Wz  = (const float*)d_in[7];
    const float* bz  = (const float*)d_in[8];
    const float* Rf  = (const float*)d_in[9];
    const float* Ri  = (const float*)d_in[10];
    const float* Ro  = (const float*)d_in[11];
    const float* Rz  = (const float*)d_in[12];
    const float* fcw = (const float*)d_in[13];
    const float* fcb = (const float*)d_in[14];
    float* out = (float*)d_out;

    cudaFuncSetAttribute(recurrent_kernel,
                         cudaFuncAttributeMaxDynamicSharedMemorySize, SMB_TOT);
    cudaFuncSetAttribute(proj_mma_kernel,
                         cudaFuncAttributeMaxDynamicSharedMemorySize, PJ_TOT);

    init_kernel<<<(2 * B_ * H_ + 255) / 256, 256>>>();

    split_x_kernel<<<(B_ * T_ * 32) / 256, 256>>>(x);
    split_w_kernel<<<(NG * 32) / 256, 256>>>(Wf, bf, Wi, bi, Wo, bo, Wz, bz);

    dim3 gP(NG / 64, T_);
    proj_mma_kernel<<<gP, 256, PJ_TOT>>>();

    recurrent_kernel<<<NBLK, NTHR, SMB_TOT>>>(Rf, Ri, Ro, Rz);

    head_kernel<<<B_, 128>>>(fcw, fcb, out);
}

// round 15
// speedup vs baseline: 1.0623x; 1.0623x over previous
#include <cuda_runtime.h>
#include <cuda_bf16.h>
#include <math.h>
#include <stdint.h>

#define B_ 128
#define T_ 512
#define F_ 256
#define H_ 512
#define NG 2048               // H_*4 fused gate cols, n = h*4+g
#define NBLK 128
#define NTHR 256

// ---------------- device globals (allocation-free scratch) ------------------
__device__ float g_xproj[(size_t)T_ * B_ * NG];             // [t][b][n]
__device__ unsigned char g_xs[2][(size_t)B_ * T_ * F_ * 2]; // bf16 hi/lo, pre-swizzled
__device__ unsigned char g_wt[2][(size_t)NG * F_ * 2];      // bf16 hi/lo W^T, pre-swizzled
__device__ float g_bc[NG];                                  // fused bias
__device__ __nv_bfloat16 g_hbf[2][2][B_][H_];               // [parity][hi/lo][b][k]
__device__ volatile unsigned g_arrive4[4 * 32];             // 128B-spaced per-group
__device__ volatile unsigned g_release4[4 * 32];

// ---------------------------------------------------------------------------
__device__ __forceinline__ uint32_t smem_u32(const void* p) {
    uint32_t a;
    asm("{ .reg .u64 t; cvta.to.shared.u64 t, %1; cvt.u32.u64 %0, t; }" : "=r"(a) : "l"(p));
    return a;
}
__device__ __forceinline__ void cpasync16(uint32_t dst_smem, const void* src) {
    asm volatile("cp.async.cg.shared.global [%0], [%1], 16;\n"
                 :: "r"(dst_smem), "l"(src));
}
__device__ __forceinline__ void ldsm4(uint32_t* r, uint32_t addr) {
    asm volatile("ldmatrix.sync.aligned.m8n8.x4.shared.b16 {%0,%1,%2,%3}, [%4];"
                 : "=r"(r[0]), "=r"(r[1]), "=r"(r[2]), "=r"(r[3]) : "r"(addr));
}
__device__ __forceinline__ void mma16816(float* d, const uint32_t* a,
                                         uint32_t b0, uint32_t b1) {
    asm volatile(
        "mma.sync.aligned.m16n8k16.row.col.f32.bf16.bf16.f32 "
        "{%0,%1,%2,%3}, {%4,%5,%6,%7}, {%8,%9}, {%0,%1,%2,%3};"
        : "+f"(d[0]), "+f"(d[1]), "+f"(d[2]), "+f"(d[3])
        : "r"(a[0]), "r"(a[1]), "r"(a[2]), "r"(a[3]), "r"(b0), "r"(b1));
}

// ---------------------------------------------------------------------------
__global__ void init_kernel() {
    int i = blockIdx.x * blockDim.x + threadIdx.x;
    if (i < 2 * B_ * H_) ((__nv_bfloat16*)g_hbf[0])[i] = __float2bfloat16(0.f);
    if (i < 4 * 32) { g_arrive4[i] = 0u; g_release4[i] = 0u; }
}

// ---------------------------------------------------------------------------
__global__ __launch_bounds__(256) void split_x_kernel(const float* __restrict__ x) {
    int idx = blockIdx.x * 256 + threadIdx.x;
    int m = idx >> 5;
    int u = idx & 31;
    float v[8];
    *(float4*)&v[0] = *(const float4*)&x[(size_t)m * F_ + u * 8];
    *(float4*)&v[4] = *(const float4*)&x[(size_t)m * F_ + u * 8 + 4];
    __nv_bfloat16 hi[8], lo[8];
#pragma unroll
    for (int i = 0; i < 8; i++) {
        hi[i] = __float2bfloat16(v[i]);
        lo[i] = __float2bfloat16(v[i] - __bfloat162float(hi[i]));
    }
    int key = (m >> 9) & 7;
    size_t dst = (size_t)m * 512 + ((u ^ key) << 4);
    *(uint4*)(g_xs[0] + dst) = *(uint4*)hi;
    *(uint4*)(g_xs[1] + dst) = *(uint4*)lo;
}

// ---------------------------------------------------------------------------
__global__ __launch_bounds__(256) void split_w_kernel(
    const float* __restrict__ W0, const float* __restrict__ b0v,
    const float* __restrict__ W1, const float* __restrict__ b1v,
    const float* __restrict__ W2, const float* __restrict__ b2v,
    const float* __restrict__ W3, const float* __restrict__ b3v)
{
    int idx = blockIdx.x * 256 + threadIdx.x;
    int n = idx >> 5;
    int u = idx & 31;
    int h = n >> 2, g = n & 3;
    const float* W = (g == 0) ? W0 : (g == 1) ? W1 : (g == 2) ? W2 : W3;
    __nv_bfloat16 hi[8], lo[8];
#pragma unroll
    for (int i = 0; i < 8; i++) {
        float v = W[(size_t)(u * 8 + i) * H_ + h];
        hi[i] = __float2bfloat16(v);
        lo[i] = __float2bfloat16(v - __bfloat162float(hi[i]));
    }
    size_t dst = (size_t)n * 512 + ((u ^ (n & 7)) << 4);
    *(uint4*)(g_wt[0] + dst) = *(uint4*)hi;
    *(uint4*)(g_wt[1] + dst) = *(uint4*)lo;
    if (u == 0) {
        const float* bias = (g == 0) ? b0v : (g == 1) ? b1v : (g == 2) ? b2v : b3v;
        g_bc[n] = bias[h];
    }
}

// ---------------------------------------------------------------------------
// Proj GEMM (tensor), RETILED: warps = wm(4) x wn(2), each m32 x n32.
// Per k16: 4 A-ldsm + 4 B-ldsm for 24 mma (was 10 ldsm / 24 mma).
// ---------------------------------------------------------------------------
#define PJ_A   0
#define PJ_B   65536
#define PJ_TOT 98304

__global__ __launch_bounds__(256) void proj_mma_kernel() {
    extern __shared__ __align__(1024) char smem[];
    const uint32_t sb = smem_u32(smem);

    const int t    = blockIdx.y;
    const int n0   = blockIdx.x * 64;
    const int tid  = threadIdx.x;
    const int w    = tid >> 5;
    const int lane = tid & 31;
    const int wm   = w >> 1;        // 0..3: m rows wm*32..+32
    const int wn   = w & 1;         // 0..1: n cols wn*32..+32
    const int lrow = lane & 15;
    const int lku  = lane >> 4;

    float2 bias_r[2][2];
#pragma unroll
    for (int nt = 0; nt < 2; nt++)
#pragma unroll
        for (int hf = 0; hf < 2; hf++) {
            int col = n0 + wn * 32 + nt * 16 + hf * 8 + (lane & 3) * 2;
            bias_r[nt][hf] = *(const float2*)&g_bc[col];
        }

    auto load_chunk = [&](int c, int buf) {
#pragma unroll
        for (int i = 0; i < 8; i++) {
            int lin = i * 256 + tid;
            int hl = lin >> 10;
            int r  = lin & 1023;
            int b  = r >> 3;
            int uu = r & 7;
            const void* src = g_xs[hl] + ((size_t)(b * T_ + t) * 512 + c * 128 + uu * 16);
            cpasync16(sb + PJ_A + buf * 32768 + hl * 16384 + b * 128 + uu * 16, src);
        }
#pragma unroll
        for (int i = 0; i < 4; i++) {
            int lin = i * 256 + tid;
            int hl = lin >> 9;
            int r  = lin & 511;
            int nl = r >> 3;
            int uu = r & 7;
            const void* src = g_wt[hl] + ((size_t)(n0 + nl) * 512 + c * 128 + uu * 16);
            cpasync16(sb + PJ_B + buf * 16384 + hl * 8192 + nl * 128 + uu * 16, src);
        }
        asm volatile("cp.async.commit_group;\n");
    };

    load_chunk(0, 0);

    float acc[2][2][2][4] = {};   // [mt][nt][hf][4]

    for (int c = 0; c < 4; c++) {
        const int buf = c & 1;
        asm volatile("cp.async.wait_group 0;\n" ::: "memory");
        __syncthreads();
        if (c + 1 < 4) load_chunk(c + 1, buf ^ 1);

        const uint32_t asw = (uint32_t)(lrow & 7);
        const uint32_t a_base = sb + PJ_A + buf * 32768;
        const uint32_t b_base = sb + PJ_B + buf * 16384;

#pragma unroll
        for (int j = 0; j < 4; j++) {
            uint32_t au = (uint32_t)(j * 2 + lku);
            uint32_t aoff = (au ^ asw) << 4;

            uint32_t ah[2][4], al[2][4], bh[2][4], bl[2][4];
#pragma unroll
            for (int mt = 0; mt < 2; mt++) {
                uint32_t arow = a_base + (wm * 32 + mt * 16 + lrow) * 128 + aoff;
                ldsm4(ah[mt], arow);
                ldsm4(al[mt], arow + 16384);
            }
#pragma unroll
            for (int nt = 0; nt < 2; nt++) {
                uint32_t brow = b_base + (wn * 32 + nt * 16 + lrow) * 128 + aoff;
                ldsm4(bh[nt], brow);
                ldsm4(bl[nt], brow + 8192);
            }

#pragma unroll
            for (int mt = 0; mt < 2; mt++)
#pragma unroll
                for (int nt = 0; nt < 2; nt++) {
                    mma16816(acc[mt][nt][0], ah[mt], bh[nt][0], bh[nt][2]);
                    mma16816(acc[mt][nt][0], ah[mt], bl[nt][0], bl[nt][2]);
                    mma16816(acc[mt][nt][0], al[mt], bh[nt][0], bh[nt][2]);
                    mma16816(acc[mt][nt][1], ah[mt], bh[nt][1], bh[nt][3]);
                    mma16816(acc[mt][nt][1], ah[mt], bl[nt][1], bl[nt][3]);
                    mma16816(acc[mt][nt][1], al[mt], bh[nt][1], bh[nt][3]);
                }
        }
        __syncthreads();
    }

#pragma unroll
    for (int mt = 0; mt < 2; mt++) {
        int r0 = wm * 32 + mt * 16 + (lane >> 2);
#pragma unroll
        for (int nt = 0; nt < 2; nt++)
#pragma unroll
            for (int hf = 0; hf < 2; hf++) {
                int col = n0 + wn * 32 + nt * 16 + hf * 8 + (lane & 3) * 2;
                float2 bb = bias_r[nt][hf];
                *(float2*)&g_xproj[((size_t)t * B_ + r0) * NG + col] =
                    make_float2(acc[mt][nt][hf][0] + bb.x, acc[mt][nt][hf][1] + bb.y);
                *(float2*)&g_xproj[((size_t)t * B_ + r0 + 8) * NG + col] =
                    make_float2(acc[mt][nt][hf][2] + bb.x, acc[mt][nt][hf][3] + bb.y);
            }
    }
}

// ---------------------------------------------------------------------------
// Persistent recurrent kernel — EXACT R13 (split-K warps, single-shot A load,
// per-bg group barrier).
// ---------------------------------------------------------------------------
#define SMB_A    0            // [2 hl][8 kt][32 m][128B] = 65536
#define SMB_B    65536        // [2 hl][64 n][1024 B]     = 131072
#define SMB_XS   196608       // [32 b][272 B] = 8704
#define SMB_PRE  205312       // 2 x float[64 n][36 m] = 18432
#define SMB_TOT  223744

__global__ __launch_bounds__(NTHR) void recurrent_kernel(
    const float* __restrict__ Rf, const float* __restrict__ Ri,
    const float* __restrict__ Ro, const float* __restrict__ Rz)
{
    extern __shared__ __align__(1024) char smem[];
    const uint32_t sb = smem_u32(smem);

    const int bid  = blockIdx.x;
    const int tid  = threadIdx.x;
    const int w    = tid >> 5;
    const int lane = tid & 31;
    const int bg   = bid >> 5;       // batch group 0..3
    const int cg   = bid & 31;       // col group 0..31

    float* xsf = (float*)(smem + SMB_XS);
    float* pre = (float*)(smem + SMB_PRE);   // two banks of 2304 floats

    // stage split R^T slice (once): row n = h_loc*4+g (64 rows), 512 k
    {
        const float* Rm[4] = {Rf, Ri, Ro, Rz};
        for (int idx = tid; idx < 64 * H_; idx += NTHR) {
            int n = idx & 63;
            int k = idx >> 6;
            int hl = n >> 2, g = n & 3;
            float v = Rm[g][(size_t)k * H_ + cg * 16 + hl];
            __nv_bfloat16 vhi = __float2bfloat16(v);
            __nv_bfloat16 vlo = __float2bfloat16(v - __bfloat162float(vhi));
            uint32_t off = n * 1024 + ((((uint32_t)k >> 3) ^ (n & 7)) << 4) + (k & 7) * 2;
            *(__nv_bfloat16*)(smem + SMB_B + off) = vhi;
            *(__nv_bfloat16*)(smem + SMB_B + 65536 + off) = vlo;
        }
    }

    // prefetch xproj[0] slice
    {
#pragma unroll
        for (int e = 0; e < 2; e++) {
            int idx = e * NTHR + tid;
            int b = idx >> 4, u = idx & 15;
            const void* src = g_xproj + (size_t)(bg * 32 + b) * NG + cg * 64 + u * 4;
            cpasync16(sb + SMB_XS + b * 272 + u * 16, src);
        }
        asm volatile("cp.async.commit_group;\n");
    }
    __syncthreads();

    // split-K MMA mapping: wn = n-tile (16 cols), wk = k-half (256 k)
    const int wn = w & 3;
    const int wk = w >> 2;
    const int lrow = lane & 15;
    const int lku  = lane >> 4;
    const uint32_t lsw    = (uint32_t)(lrow & 7);
    const uint32_t a_base = sb + SMB_A + lrow * 128;
    const uint32_t b_base = sb + SMB_B + (wn * 16 + lrow) * 1024;
    float* preh = pre + wk * 2304;

    // update mapping
    const int ub = tid >> 3;
    const int uq = tid & 7;
    float c_reg[2] = {0.f, 0.f};
    float n_reg[2] = {0.f, 0.f};

    volatile unsigned* arr = &g_arrive4[bg * 32];
    volatile unsigned* rel = &g_release4[bg * 32];
    unsigned epoch = 0;

    for (int t = 0; t < T_; t++) {
        const int par = t & 1;
        const __nv_bfloat16* __restrict__ hsrc = &g_hbf[par][0][0][0];

        // ---- single-shot A load: all K=512, hi+lo = 64KB (16 x 16B / thread) ----
        {
#pragma unroll
            for (int i = 0; i < 16; i++) {
                int lin = i * NTHR + tid;      // 0..4095
                int hl = lin >> 11;
                int r  = lin & 2047;
                int kt = r >> 8;
                int m  = (r >> 3) & 31;
                int s  = r & 7;
                const __nv_bfloat16* src =
                    hsrc + ((size_t)hl * B_ + bg * 32 + m) * H_ + kt * 64 + s * 8;
                cpasync16(sb + SMB_A + hl * 32768 + kt * 4096 +
                          m * 128 + ((s ^ (m & 7)) << 4), src);
            }
            asm volatile("cp.async.commit_group;\n");
            asm volatile("cp.async.wait_group 0;\n" ::: "memory");
        }
        __syncthreads();

        float acc[2][2][4] = {};   // [mt][n8][4]

#pragma unroll
        for (int j = 0; j < 16; j++) {
            const int kt = wk * 4 + (j >> 2);
            const uint32_t au = (uint32_t)((j & 3) * 2 + lku);
            const uint32_t bu = (uint32_t)(wk * 32 + j * 2 + lku);

            const uint32_t a_hi0 = a_base + kt * 4096 + ((au ^ lsw) << 4);
            const uint32_t a_hi1 = a_hi0 + 2048;
            const uint32_t b_hi  = b_base + ((bu ^ lsw) << 4);

            uint32_t ah0[4], ah1[4], al0[4], al1[4], bh[4], bl[4];
            ldsm4(ah0, a_hi0);
            ldsm4(ah1, a_hi1);
            ldsm4(al0, a_hi0 + 32768);
            ldsm4(al1, a_hi1 + 32768);
            ldsm4(bh, b_hi);
            ldsm4(bl, b_hi + 65536);

            mma16816(acc[0][0], ah0, bh[0], bh[2]);
            mma16816(acc[0][0], ah0, bl[0], bl[2]);
            mma16816(acc[0][0], al0, bh[0], bh[2]);
            mma16816(acc[0][1], ah0, bh[1], bh[3]);
            mma16816(acc[0][1], ah0, bl[1], bl[3]);
            mma16816(acc[0][1], al0, bh[1], bh[3]);

            mma16816(acc[1][0], ah1, bh[0], bh[2]);
            mma16816(acc[1][0], ah1, bl[0], bl[2]);
            mma16816(acc[1][0], al1, bh[0], bh[2]);
            mma16816(acc[1][1], ah1, bh[1], bh[3]);
            mma16816(acc[1][1], ah1, bl[1], bl[3]);
            mma16816(acc[1][1], al1, bh[1], bh[3]);
        }

        // epilogue: D fragments -> preh[n][m] (bank wk, stride 36)
        {
            int r0 = lane >> 2;
#pragma unroll
            for (int mt = 0; mt < 2; mt++) {
                int row0 = mt * 16 + r0;
#pragma unroll
                for (int n8 = 0; n8 < 2; n8++) {
                    int col0 = wn * 16 + n8 * 8 + (lane & 3) * 2;
                    preh[(col0    ) * 36 + row0    ] = acc[mt][n8][0];
                    preh[(col0 + 1) * 36 + row0    ] = acc[mt][n8][1];
                    preh[(col0    ) * 36 + row0 + 8] = acc[mt][n8][2];
                    preh[(col0 + 1) * 36 + row0 + 8] = acc[mt][n8][3];
                }
            }
        }
        __syncthreads();

        // pointwise sLSTM update (sum the two k-half banks)
        {
            const int np = par ^ 1;
            const int gb = bg * 32 + ub;
            uint32_t phi, plo;
            __nv_bfloat16* vhi = (__nv_bfloat16*)&phi;
            __nv_bfloat16* vlo = (__nv_bfloat16*)&plo;
#pragma unroll
            for (int e = 0; e < 2; e++) {
                int hc = uq * 2 + e;
                float ft = pre[(hc * 4 + 0) * 36 + ub] + pre[2304 + (hc * 4 + 0) * 36 + ub]
                         + xsf[ub * 68 + hc * 4 + 0];
                float it = pre[(hc * 4 + 1) * 36 + ub] + pre[2304 + (hc * 4 + 1) * 36 + ub]
                         + xsf[ub * 68 + hc * 4 + 1];
                float ot = pre[(hc * 4 + 2) * 36 + ub] + pre[2304 + (hc * 4 + 2) * 36 + ub]
                         + xsf[ub * 68 + hc * 4 + 2];
                float zt = pre[(hc * 4 + 3) * 36 + ub] + pre[2304 + (hc * 4 + 3) * 36 + ub]
                         + xsf[ub * 68 + hc * 4 + 3];

                float o  = __fdividef(1.f, 1.f + __expf(-ot));
                float z  = 1.f - __fdividef(2.f, __expf(2.f * zt) + 1.f);
                float fh = __expf(fminf(ft, 10.f));
                float ih = __expf(fminf(it, 10.f));
                float rd = __fdividef(1.f, fh + ih + 1e-8f);
                float f  = fh * rd;
                float ii = ih * rd;
                c_reg[e] = f * c_reg[e] + ii * z;
                n_reg[e] = f * n_reg[e] + ii;
                float hv = o * __fdividef(c_reg[e], n_reg[e] + 1e-8f);

                vhi[e] = __float2bfloat16(hv);
                vlo[e] = __float2bfloat16(hv - __bfloat162float(vhi[e]));
            }
            *(uint32_t*)&g_hbf[np][0][gb][cg * 16 + uq * 2] = phi;
            *(uint32_t*)&g_hbf[np][1][gb][cg * 16 + uq * 2] = plo;
        }

        __syncthreads();

        // prefetch xproj[t+1] in barrier shadow
        if (t + 1 < T_) {
#pragma unroll
            for (int e = 0; e < 2; e++) {
                int idx = e * NTHR + tid;
                int b = idx >> 4, u = idx & 15;
                const void* src = g_xproj + ((size_t)(t + 1) * B_ + bg * 32 + b) * NG
                                + cg * 64 + u * 4;
                cpasync16(sb + SMB_XS + b * 272 + u * 16, src);
            }
            asm volatile("cp.async.commit_group;\n");
        }

        // ---- per-bg group barrier (32 blocks) ----
        epoch++;
        if (tid == 0) {
            __threadfence();
            unsigned a = atomicAdd((unsigned*)arr, 1u) + 1u;
            if (a == epoch * 32) {
                *rel = epoch;
                __threadfence();
            } else {
                while (*rel < epoch) { }
                __threadfence();
            }
        }
        __syncthreads();
    }

    asm volatile("cp.async.wait_group 0;\n" ::: "memory");
}

// ---------------------------------------------------------------------------
__global__ __launch_bounds__(128) void head_kernel(
    const float* __restrict__ fcw, const float* __restrict__ fcb,
    float* __restrict__ out)
{
    int b = blockIdx.x;
    float s = 0.f;
    for (int k = threadIdx.x; k < H_; k += 128) {
        float hv = __bfloat162float(g_hbf[0][0][b][k]) +
                   __bfloat162float(g_hbf[0][1][b][k]);
        s += hv * fcw[k];
    }

    __shared__ float red[4];
#pragma unroll
    for (int off = 16; off; off >>= 1)
        s += __shfl_down_sync(0xffffffff, s, off);
    if ((threadIdx.x & 31) == 0) red[threadIdx.x >> 5] = s;
    __syncthreads();
    if (threadIdx.x == 0) {
        float tot = red[0] + red[1] + red[2] + red[3];
        out[b] = tanhf(tot + fcb[0]);
    }
}

// ---------------------------------------------------------------------------
extern "C" void kernel_launch(void* const* d_in, const int* in_sizes, int n_in,
                              void* d_out, int out_size)
{
    const float* x   = (const float*)d_in[0];
    const float* Wf  = (const float*)d_in[1];
    const float* bf  = (const float*)d_in[2];
    const float* Wi  = (const float*)d_in[3];
    const float* bi  = (const float*)d_in[4];
    const float* Wo  = (const float*)d_in[5];
    const float* bo  = (const float*)d_in[6];
    const float* Wz  = (const float*)d_in[7];
    const float* bz  = (const float*)d_in[8];
    const float* Rf  = (const float*)d_in[9];
    const float* Ri  = (const float*)d_in[10];
    const float* Ro  = (const float*)d_in[11];
    const float* Rz  = (const float*)d_in[12];
    const float* fcw = (const float*)d_in[13];
    const float* fcb = (const float*)d_in[14];
    float* out = (float*)d_out;

    cudaFuncSetAttribute(recurrent_kernel,
                         cudaFuncAttributeMaxDynamicSharedMemorySize, SMB_TOT);
    cudaFuncSetAttribute(proj_mma_kernel,
                         cudaFuncAttributeMaxDynamicSharedMemorySize, PJ_TOT);

    init_kernel<<<(2 * B_ * H_ + 255) / 256, 256>>>();

    split_x_kernel<<<(B_ * T_ * 32) / 256, 256>>>(x);
    split_w_kernel<<<(NG * 32) / 256, 256>>>(Wf, bf, Wi, bi, Wo, bo, Wz, bz);

    dim3 gP(NG / 64, T_);
    proj_mma_kernel<<<gP, 256, PJ_TOT>>>();

    recurrent_kernel<<<NBLK, NTHR, SMB_TOT>>>(Rf, Ri, Ro, Rz);

    head_kernel<<<B_, 128>>>(fcw, fcb, out);
}

// round 16
// speedup vs baseline: 1.0784x; 1.0152x over previous
#include <cuda_runtime.h>
#include <cuda_bf16.h>
#include <math.h>
#include <stdint.h>

#define B_ 128
#define T_ 512
#define F_ 256
#define H_ 512
#define NG 2048               // H_*4 fused gate cols, n = h*4+g
#define NBLK 128
#define NTHR 256

// ---------------- device globals (allocation-free scratch) ------------------
__device__ float g_xproj[(size_t)T_ * B_ * NG];             // [t][b][n]
__device__ unsigned char g_xs[2][(size_t)B_ * T_ * F_ * 2]; // bf16 hi/lo, pre-swizzled
__device__ unsigned char g_wt[2][(size_t)NG * F_ * 2];      // bf16 hi/lo W^T, pre-swizzled
__device__ float g_bc[NG];                                  // fused bias
__device__ __nv_bfloat16 g_hbf[2][2][B_][H_];               // [parity][hi/lo][b][k]
__device__ volatile unsigned g_arrive4[4 * 32];             // 128B-spaced per-group
__device__ volatile unsigned g_release4[4 * 32];

// ---------------------------------------------------------------------------
__device__ __forceinline__ uint32_t smem_u32(const void* p) {
    uint32_t a;
    asm("{ .reg .u64 t; cvta.to.shared.u64 t, %1; cvt.u32.u64 %0, t; }" : "=r"(a) : "l"(p));
    return a;
}
__device__ __forceinline__ void cpasync16(uint32_t dst_smem, const void* src) {
    asm volatile("cp.async.cg.shared.global [%0], [%1], 16;\n"
                 :: "r"(dst_smem), "l"(src));
}
__device__ __forceinline__ void ldsm4(uint32_t* r, uint32_t addr) {
    asm volatile("ldmatrix.sync.aligned.m8n8.x4.shared.b16 {%0,%1,%2,%3}, [%4];"
                 : "=r"(r[0]), "=r"(r[1]), "=r"(r[2]), "=r"(r[3]) : "r"(addr));
}
__device__ __forceinline__ void mma16816(float* d, const uint32_t* a,
                                         uint32_t b0, uint32_t b1) {
    asm volatile(
        "mma.sync.aligned.m16n8k16.row.col.f32.bf16.bf16.f32 "
        "{%0,%1,%2,%3}, {%4,%5,%6,%7}, {%8,%9}, {%0,%1,%2,%3};"
        : "+f"(d[0]), "+f"(d[1]), "+f"(d[2]), "+f"(d[3])
        : "r"(a[0]), "r"(a[1]), "r"(a[2]), "r"(a[3]), "r"(b0), "r"(b1));
}

// ---------------------------------------------------------------------------
__global__ void init_kernel() {
    int i = blockIdx.x * blockDim.x + threadIdx.x;
    if (i < 2 * B_ * H_) ((__nv_bfloat16*)g_hbf[0])[i] = __float2bfloat16(0.f);
    if (i < 4 * 32) { g_arrive4[i] = 0u; g_release4[i] = 0u; }
}

// ---------------------------------------------------------------------------
__global__ __launch_bounds__(256) void split_x_kernel(const float* __restrict__ x) {
    int idx = blockIdx.x * 256 + threadIdx.x;
    int m = idx >> 5;
    int u = idx & 31;
    float v[8];
    *(float4*)&v[0] = *(const float4*)&x[(size_t)m * F_ + u * 8];
    *(float4*)&v[4] = *(const float4*)&x[(size_t)m * F_ + u * 8 + 4];
    __nv_bfloat16 hi[8], lo[8];
#pragma unroll
    for (int i = 0; i < 8; i++) {
        hi[i] = __float2bfloat16(v[i]);
        lo[i] = __float2bfloat16(v[i] - __bfloat162float(hi[i]));
    }
    int key = (m >> 9) & 7;
    size_t dst = (size_t)m * 512 + ((u ^ key) << 4);
    *(uint4*)(g_xs[0] + dst) = *(uint4*)hi;
    *(uint4*)(g_xs[1] + dst) = *(uint4*)lo;
}

// ---------------------------------------------------------------------------
__global__ __launch_bounds__(256) void split_w_kernel(
    const float* __restrict__ W0, const float* __restrict__ b0v,
    const float* __restrict__ W1, const float* __restrict__ b1v,
    const float* __restrict__ W2, const float* __restrict__ b2v,
    const float* __restrict__ W3, const float* __restrict__ b3v)
{
    int idx = blockIdx.x * 256 + threadIdx.x;
    int n = idx >> 5;
    int u = idx & 31;
    int h = n >> 2, g = n & 3;
    const float* W = (g == 0) ? W0 : (g == 1) ? W1 : (g == 2) ? W2 : W3;
    __nv_bfloat16 hi[8], lo[8];
#pragma unroll
    for (int i = 0; i < 8; i++) {
        float v = W[(size_t)(u * 8 + i) * H_ + h];
        hi[i] = __float2bfloat16(v);
        lo[i] = __float2bfloat16(v - __bfloat162float(hi[i]));
    }
    size_t dst = (size_t)n * 512 + ((u ^ (n & 7)) << 4);
    *(uint4*)(g_wt[0] + dst) = *(uint4*)hi;
    *(uint4*)(g_wt[1] + dst) = *(uint4*)lo;
    if (u == 0) {
        const float* bias = (g == 0) ? b0v : (g == 1) ? b1v : (g == 2) ? b2v : b3v;
        g_bc[n] = bias[h];
    }
}

// ---------------------------------------------------------------------------
// Proj GEMM (tensor), M64 x N64 tiles, 64KB smem -> 3 CTAs/SM.
// Warp tile m16 x n32 (wm 0..3, wn 0..1). Grid (32, 1024): by = t*2 + m-half.
// ---------------------------------------------------------------------------
#define PJ_A   0              // [2 buf][2 hl][64 m][128B] = 32768
#define PJ_B   32768          // [2 buf][2 hl][64 n][128B] = 32768
#define PJ_TOT 65536

__global__ __launch_bounds__(256, 3) void proj_mma_kernel() {
    extern __shared__ __align__(1024) char smem[];
    const uint32_t sb = smem_u32(smem);

    const int t    = blockIdx.y >> 1;
    const int m0   = (blockIdx.y & 1) * 64;
    const int n0   = blockIdx.x * 64;
    const int tid  = threadIdx.x;
    const int w    = tid >> 5;
    const int lane = tid & 31;
    const int wm   = w >> 1;        // 0..3: m rows wm*16..+16
    const int wn   = w & 1;         // 0..1: n cols wn*32..+32
    const int lrow = lane & 15;
    const int lku  = lane >> 4;

    float2 bias_r[2][2];
#pragma unroll
    for (int nt = 0; nt < 2; nt++)
#pragma unroll
        for (int hf = 0; hf < 2; hf++) {
            int col = n0 + wn * 32 + nt * 16 + hf * 8 + (lane & 3) * 2;
            bias_r[nt][hf] = *(const float2*)&g_bc[col];
        }

    auto load_chunk = [&](int c, int buf) {
        // A: 2hl x 64 rows x 8 u = 1024 x16B -> 4 per thread
#pragma unroll
        for (int i = 0; i < 4; i++) {
            int lin = i * 256 + tid;
            int hl = lin >> 9;
            int r  = lin & 511;
            int b  = r >> 3;
            int uu = r & 7;
            const void* src =
                g_xs[hl] + ((size_t)((m0 + b) * T_ + t) * 512 + c * 128 + uu * 16);
            cpasync16(sb + PJ_A + buf * 16384 + hl * 8192 + b * 128 + uu * 16, src);
        }
        // B: 2hl x 64 rows x 8 u = 1024 x16B -> 4 per thread
#pragma unroll
        for (int i = 0; i < 4; i++) {
            int lin = i * 256 + tid;
            int hl = lin >> 9;
            int r  = lin & 511;
            int nl = r >> 3;
            int uu = r & 7;
            const void* src = g_wt[hl] + ((size_t)(n0 + nl) * 512 + c * 128 + uu * 16);
            cpasync16(sb + PJ_B + buf * 16384 + hl * 8192 + nl * 128 + uu * 16, src);
        }
        asm volatile("cp.async.commit_group;\n");
    };

    load_chunk(0, 0);

    float acc[2][2][4] = {};   // [nt][hf][4]

    for (int c = 0; c < 4; c++) {
        const int buf = c & 1;
        asm volatile("cp.async.wait_group 0;\n" ::: "memory");
        __syncthreads();
        if (c + 1 < 4) load_chunk(c + 1, buf ^ 1);

        const uint32_t asw    = (uint32_t)(lrow & 7);
        const uint32_t a_base = sb + PJ_A + buf * 16384 + (wm * 16 + lrow) * 128;
        const uint32_t b_base = sb + PJ_B + buf * 16384;

#pragma unroll
        for (int j = 0; j < 4; j++) {
            uint32_t aoff = (((uint32_t)(j * 2 + lku)) ^ asw) << 4;

            uint32_t ah[4], al[4];
            ldsm4(ah, a_base + aoff);
            ldsm4(al, a_base + 8192 + aoff);

#pragma unroll
            for (int nt = 0; nt < 2; nt++) {
                uint32_t brow = b_base + (wn * 32 + nt * 16 + lrow) * 128 + aoff;
                uint32_t bh[4], bl[4];
                ldsm4(bh, brow);
                ldsm4(bl, brow + 8192);

                mma16816(acc[nt][0], ah, bh[0], bh[2]);
                mma16816(acc[nt][0], ah, bl[0], bl[2]);
                mma16816(acc[nt][0], al, bh[0], bh[2]);
                mma16816(acc[nt][1], ah, bh[1], bh[3]);
                mma16816(acc[nt][1], ah, bl[1], bl[3]);
                mma16816(acc[nt][1], al, bh[1], bh[3]);
            }
        }
        __syncthreads();
    }

    const int r0 = m0 + wm * 16 + (lane >> 2);
#pragma unroll
    for (int nt = 0; nt < 2; nt++)
#pragma unroll
        for (int hf = 0; hf < 2; hf++) {
            int col = n0 + wn * 32 + nt * 16 + hf * 8 + (lane & 3) * 2;
            float2 bb = bias_r[nt][hf];
            *(float2*)&g_xproj[((size_t)t * B_ + r0) * NG + col] =
                make_float2(acc[nt][hf][0] + bb.x, acc[nt][hf][1] + bb.y);
            *(float2*)&g_xproj[((size_t)t * B_ + r0 + 8) * NG + col] =
                make_float2(acc[nt][hf][2] + bb.x, acc[nt][hf][3] + bb.y);
        }
}

// ---------------------------------------------------------------------------
// Persistent recurrent kernel — EXACT R13/R15 (split-K warps, single-shot A
// load, per-bg group barrier).
// ---------------------------------------------------------------------------
#define SMB_A    0            // [2 hl][8 kt][32 m][128B] = 65536
#define SMB_B    65536        // [2 hl][64 n][1024 B]     = 131072
#define SMB_XS   196608       // [32 b][272 B] = 8704
#define SMB_PRE  205312       // 2 x float[64 n][36 m] = 18432
#define SMB_TOT  223744

__global__ __launch_bounds__(NTHR) void recurrent_kernel(
    const float* __restrict__ Rf, const float* __restrict__ Ri,
    const float* __restrict__ Ro, const float* __restrict__ Rz)
{
    extern __shared__ __align__(1024) char smem[];
    const uint32_t sb = smem_u32(smem);

    const int bid  = blockIdx.x;
    const int tid  = threadIdx.x;
    const int w    = tid >> 5;
    const int lane = tid & 31;
    const int bg   = bid >> 5;       // batch group 0..3
    const int cg   = bid & 31;       // col group 0..31

    float* xsf = (float*)(smem + SMB_XS);
    float* pre = (float*)(smem + SMB_PRE);   // two banks of 2304 floats

    // stage split R^T slice (once): row n = h_loc*4+g (64 rows), 512 k
    {
        const float* Rm[4] = {Rf, Ri, Ro, Rz};
        for (int idx = tid; idx < 64 * H_; idx += NTHR) {
            int n = idx & 63;
            int k = idx >> 6;
            int hl = n >> 2, g = n & 3;
            float v = Rm[g][(size_t)k * H_ + cg * 16 + hl];
            __nv_bfloat16 vhi = __float2bfloat16(v);
            __nv_bfloat16 vlo = __float2bfloat16(v - __bfloat162float(vhi));
            uint32_t off = n * 1024 + ((((uint32_t)k >> 3) ^ (n & 7)) << 4) + (k & 7) * 2;
            *(__nv_bfloat16*)(smem + SMB_B + off) = vhi;
            *(__nv_bfloat16*)(smem + SMB_B + 65536 + off) = vlo;
        }
    }

    // prefetch xproj[0] slice
    {
#pragma unroll
        for (int e = 0; e < 2; e++) {
            int idx = e * NTHR + tid;
            int b = idx >> 4, u = idx & 15;
            const void* src = g_xproj + (size_t)(bg * 32 + b) * NG + cg * 64 + u * 4;
            cpasync16(sb + SMB_XS + b * 272 + u * 16, src);
        }
        asm volatile("cp.async.commit_group;\n");
    }
    __syncthreads();

    // split-K MMA mapping: wn = n-tile (16 cols), wk = k-half (256 k)
    const int wn = w & 3;
    const int wk = w >> 2;
    const int lrow = lane & 15;
    const int lku  = lane >> 4;
    const uint32_t lsw    = (uint32_t)(lrow & 7);
    const uint32_t a_base = sb + SMB_A + lrow * 128;
    const uint32_t b_base = sb + SMB_B + (wn * 16 + lrow) * 1024;
    float* preh = pre + wk * 2304;

    // update mapping
    const int ub = tid >> 3;
    const int uq = tid & 7;
    float c_reg[2] = {0.f, 0.f};
    float n_reg[2] = {0.f, 0.f};

    volatile unsigned* arr = &g_arrive4[bg * 32];
    volatile unsigned* rel = &g_release4[bg * 32];
    unsigned epoch = 0;

    for (int t = 0; t < T_; t++) {
        const int par = t & 1;
        const __nv_bfloat16* __restrict__ hsrc = &g_hbf[par][0][0][0];

        // ---- single-shot A load: all K=512, hi+lo = 64KB (16 x 16B / thread) ----
        {
#pragma unroll
            for (int i = 0; i < 16; i++) {
                int lin = i * NTHR + tid;      // 0..4095
                int hl = lin >> 11;
                int r  = lin & 2047;
                int kt = r >> 8;
                int m  = (r >> 3) & 31;
                int s  = r & 7;
                const __nv_bfloat16* src =
                    hsrc + ((size_t)hl * B_ + bg * 32 + m) * H_ + kt * 64 + s * 8;
                cpasync16(sb + SMB_A + hl * 32768 + kt * 4096 +
                          m * 128 + ((s ^ (m & 7)) << 4), src);
            }
            asm volatile("cp.async.commit_group;\n");
            asm volatile("cp.async.wait_group 0;\n" ::: "memory");
        }
        __syncthreads();

        float acc[2][2][4] = {};   // [mt][n8][4]

#pragma unroll
        for (int j = 0; j < 16; j++) {
            const int kt = wk * 4 + (j >> 2);
            const uint32_t au = (uint32_t)((j & 3) * 2 + lku);
            const uint32_t bu = (uint32_t)(wk * 32 + j * 2 + lku);

            const uint32_t a_hi0 = a_base + kt * 4096 + ((au ^ lsw) << 4);
            const uint32_t a_hi1 = a_hi0 + 2048;
            const uint32_t b_hi  = b_base + ((bu ^ lsw) << 4);

            uint32_t ah0[4], ah1[4], al0[4], al1[4], bh[4], bl[4];
            ldsm4(ah0, a_hi0);
            ldsm4(ah1, a_hi1);
            ldsm4(al0, a_hi0 + 32768);
            ldsm4(al1, a_hi1 + 32768);
            ldsm4(bh, b_hi);
            ldsm4(bl, b_hi + 65536);

            mma16816(acc[0][0], ah0, bh[0], bh[2]);
            mma16816(acc[0][0], ah0, bl[0], bl[2]);
            mma16816(acc[0][0], al0, bh[0], bh[2]);
            mma16816(acc[0][1], ah0, bh[1], bh[3]);
            mma16816(acc[0][1], ah0, bl[1], bl[3]);
            mma16816(acc[0][1], al0, bh[1], bh[3]);

            mma16816(acc[1][0], ah1, bh[0], bh[2]);
            mma16816(acc[1][0], ah1, bl[0], bl[2]);
            mma16816(acc[1][0], al1, bh[0], bh[2]);
            mma16816(acc[1][1], ah1, bh[1], bh[3]);
            mma16816(acc[1][1], ah1, bl[1], bl[3]);
            mma16816(acc[1][1], al1, bh[1], bh[3]);
        }

        // epilogue: D fragments -> preh[n][m] (bank wk, stride 36)
        {
            int r0 = lane >> 2;
#pragma unroll
            for (int mt = 0; mt < 2; mt++) {
                int row0 = mt * 16 + r0;
#pragma unroll
                for (int n8 = 0; n8 < 2; n8++) {
                    int col0 = wn * 16 + n8 * 8 + (lane & 3) * 2;
                    preh[(col0    ) * 36 + row0    ] = acc[mt][n8][0];
                    preh[(col0 + 1) * 36 + row0    ] = acc[mt][n8][1];
                    preh[(col0    ) * 36 + row0 + 8] = acc[mt][n8][2];
                    preh[(col0 + 1) * 36 + row0 + 8] = acc[mt][n8][3];
                }
            }
        }
        __syncthreads();

        // pointwise sLSTM update (sum the two k-half banks)
        {
            const int np = par ^ 1;
            const int gb = bg * 32 + ub;
            uint32_t phi, plo;
            __nv_bfloat16* vhi = (__nv_bfloat16*)&phi;
            __nv_bfloat16* vlo = (__nv_bfloat16*)&plo;
#pragma unroll
            for (int e = 0; e < 2; e++) {
                int hc = uq * 2 + e;
                float ft = pre[(hc * 4 + 0) * 36 + ub] + pre[2304 + (hc * 4 + 0) * 36 + ub]
                         + xsf[ub * 68 + hc * 4 + 0];
                float it = pre[(hc * 4 + 1) * 36 + ub] + pre[2304 + (hc * 4 + 1) * 36 + ub]
                         + xsf[ub * 68 + hc * 4 + 1];
                float ot = pre[(hc * 4 + 2) * 36 + ub] + pre[2304 + (hc * 4 + 2) * 36 + ub]
                         + xsf[ub * 68 + hc * 4 + 2];
                float zt = pre[(hc * 4 + 3) * 36 + ub] + pre[2304 + (hc * 4 + 3) * 36 + ub]
                         + xsf[ub * 68 + hc * 4 + 3];

                float o  = __fdividef(1.f, 1.f + __expf(-ot));
                float z  = 1.f - __fdividef(2.f, __expf(2.f * zt) + 1.f);
                float fh = __expf(fminf(ft, 10.f));
                float ih = __expf(fminf(it, 10.f));
                float rd = __fdividef(1.f, fh + ih + 1e-8f);
                float f  = fh * rd;
                float ii = ih * rd;
                c_reg[e] = f * c_reg[e] + ii * z;
                n_reg[e] = f * n_reg[e] + ii;
                float hv = o * __fdividef(c_reg[e], n_reg[e] + 1e-8f);

                vhi[e] = __float2bfloat16(hv);
                vlo[e] = __float2bfloat16(hv - __bfloat162float(vhi[e]));
            }
            *(uint32_t*)&g_hbf[np][0][gb][cg * 16 + uq * 2] = phi;
            *(uint32_t*)&g_hbf[np][1][gb][cg * 16 + uq * 2] = plo;
        }

        __syncthreads();

        // prefetch xproj[t+1] in barrier shadow
        if (t + 1 < T_) {
#pragma unroll
            for (int e = 0; e < 2; e++) {
                int idx = e * NTHR + tid;
                int b = idx >> 4, u = idx & 15;
                const void* src = g_xproj + ((size_t)(t + 1) * B_ + bg * 32 + b) * NG
                                + cg * 64 + u * 4;
                cpasync16(sb + SMB_XS + b * 272 + u * 16, src);
            }
            asm volatile("cp.async.commit_group;\n");
        }

        // ---- per-bg group barrier (32 blocks) ----
        epoch++;
        if (tid == 0) {
            __threadfence();
            unsigned a = atomicAdd((unsigned*)arr, 1u) + 1u;
            if (a == epoch * 32) {
                *rel = epoch;
                __threadfence();
            } else {
                while (*rel < epoch) { }
                __threadfence();
            }
        }
        __syncthreads();
    }

    asm volatile("cp.async.wait_group 0;\n" ::: "memory");
}

// ---------------------------------------------------------------------------
__global__ __launch_bounds__(128) void head_kernel(
    const float* __restrict__ fcw, const float* __restrict__ fcb,
    float* __restrict__ out)
{
    int b = blockIdx.x;
    float s = 0.f;
    for (int k = threadIdx.x; k < H_; k += 128) {
        float hv = __bfloat162float(g_hbf[0][0][b][k]) +
                   __bfloat162float(g_hbf[0][1][b][k]);
        s += hv * fcw[k];
    }

    __shared__ float red[4];
#pragma unroll
    for (int off = 16; off; off >>= 1)
        s += __shfl_down_sync(0xffffffff, s, off);
    if ((threadIdx.x & 31) == 0) red[threadIdx.x >> 5] = s;
    __syncthreads();
    if (threadIdx.x == 0) {
        float tot = red[0] + red[1] + red[2] + red[3];
        out[b] = tanhf(tot + fcb[0]);
    }
}

// ---------------------------------------------------------------------------
extern "C" void kernel_launch(void* const* d_in, const int* in_sizes, int n_in,
                              void* d_out, int out_size)
{
    const float* x   = (const float*)d_in[0];
    const float* Wf  = (const float*)d_in[1];
    const float* bf  = (const float*)d_in[2];
    const float* Wi  = (const float*)d_in[3];
    const float* bi  = (const float*)d_in[4];
    const float* Wo  = (const float*)d_in[5];
    const float* bo  = (const float*)d_in[6];
    const float* Wz  = (const float*)d_in[7];
    const float* bz  = (const float*)d_in[8];
    const float* Rf  = (const float*)d_in[9];
    const float* Ri  = (const float*)d_in[10];
    const float* Ro  = (const float*)d_in[11];
    const float* Rz  = (const float*)d_in[12];
    const float* fcw = (const float*)d_in[13];
    const float* fcb = (const float*)d_in[14];
    float* out = (float*)d_out;

    cudaFuncSetAttribute(recurrent_kernel,
                         cudaFuncAttributeMaxDynamicSharedMemorySize, SMB_TOT);
    cudaFuncSetAttribute(proj_mma_kernel,
                         cudaFuncAttributeMaxDynamicSharedMemorySize, PJ_TOT);

    init_kernel<<<(2 * B_ * H_ + 255) / 256, 256>>>();

    split_x_kernel<<<(B_ * T_ * 32) / 256, 256>>>(x);
    split_w_kernel<<<(NG * 32) / 256, 256>>>(Wf, bf, Wi, bi, Wo, bo, Wz, bz);

    dim3 gP(NG / 64, T_ * 2);   // (32 n-tiles, 512 t x 2 m-halves)
    proj_mma_kernel<<<gP, 256, PJ_TOT>>>();

    recurrent_kernel<<<NBLK, NTHR, SMB_TOT>>>(Rf, Ri, Ro, Rz);

    head_kernel<<<B_, 128>>>(fcw, fcb, out);
}